// round 15
// baseline (speedup 1.0000x reference)
#include <cuda_runtime.h>
#include <math.h>

#define BATCH 8192
#define DIN   3200
#define DH    128
#define NE    5

// ---------------- scratch (static device globals: allocation-free) ----------
__device__ float g_h [BATCH * DIN];        // conv features      [B,3200]
__device__ float g_h1[BATCH * NE * DH];    // tanh(e1) outputs   [B,640]
__device__ float g_wf[BATCH * NE];         // sparse top-3 gate  [B,5]

// ---------------- f32x2 helpers (IEEE-identical to two fmaf) ----------------
__device__ __forceinline__ void fma2(unsigned long long& d,
                                     unsigned long long a,
                                     unsigned long long b) {
    asm("fma.rn.f32x2 %0, %1, %2, %0;" : "+l"(d) : "l"(a), "l"(b));
}
__device__ __forceinline__ float2 up2(unsigned long long v) {
    float2 f;
    asm("mov.b64 {%0,%1}, %2;" : "=f"(f.x), "=f"(f.y) : "l"(v));
    return f;
}

// ============================================================================
// Kernel A: conv1(5x5,16)+ReLU -> maxpool2 -> conv2(3x3,32)+ReLU -> g_h
//           + FUSED gate: softmax(h@gate_w+gate_b), top-3, renorm -> g_wf
// One block per image, 320 threads.
// ============================================================================
__global__ __launch_bounds__(320) void conv_kernel(
    const float* __restrict__ x,
    const float* __restrict__ w1, const float* __restrict__ b1,
    const float* __restrict__ w2, const float* __restrict__ b2,
    const float* __restrict__ gw, const float* __restrict__ gb)
{
    __shared__ float s_img [784];
    __shared__ float s_w1  [400];
    __shared__ float s_b1  [16];
    __shared__ float s_pool[2304];   // [16][12][12]
    __shared__ float s_w2  [4608];   // [32][16][9]
    __shared__ float s_b2  [32];
    __shared__ float s_out [3200];
    __shared__ float s_red [10][5];

    const int tid = threadIdx.x;
    const int b   = blockIdx.x;

    const float* xi = x + (size_t)b * 784;
    for (int i = tid; i < 784;  i += 320) s_img[i] = xi[i];
    for (int i = tid; i < 400;  i += 320) s_w1[i]  = w1[i];
    if (tid < 16) s_b1[tid] = b1[tid];
    for (int i = tid; i < 4608; i += 320) s_w2[i]  = w2[i];
    if (tid < 32) s_b2[tid] = b2[tid];
    __syncthreads();

    // conv1 + relu + maxpool: 6x6 input patch in REGISTERS, each weight
    // loaded once and used for all 4 window positions.
    for (int idx = tid; idx < 2304; idx += 320) {
        int oc = idx / 144, r = idx % 144;
        int py = r / 12,   px = r % 12;
        int iy = 2 * py,   ix = 2 * px;

        float p[6][6];
        #pragma unroll
        for (int yy = 0; yy < 6; yy++)
            #pragma unroll
            for (int xx = 0; xx < 6; xx++)
                p[yy][xx] = s_img[(iy + yy) * 28 + ix + xx];

        float bb = s_b1[oc];
        float v00 = bb, v01 = bb, v10 = bb, v11 = bb;
        const float* wp = &s_w1[oc * 25];
        #pragma unroll
        for (int ky = 0; ky < 5; ky++)
            #pragma unroll
            for (int kx = 0; kx < 5; kx++) {
                float w = wp[ky * 5 + kx];
                v00 += p[ky][kx]         * w;
                v01 += p[ky][kx + 1]     * w;
                v10 += p[ky + 1][kx]     * w;
                v11 += p[ky + 1][kx + 1] * w;
            }
        float best = fmaxf(fmaxf(v00, v01), fmaxf(v10, v11));
        s_pool[idx] = fmaxf(best, 0.0f);
    }
    __syncthreads();

    // conv2 + relu: thread = (oc, out-row y), full row of 10 outputs
    {
        int oc = tid / 10;
        int y  = tid % 10;
        float acc[10];
        float bb = s_b2[oc];
        #pragma unroll
        for (int j = 0; j < 10; j++) acc[j] = bb;

        for (int ic = 0; ic < 16; ic++) {
            const float* pin = &s_pool[ic * 144];
            const float* pw  = &s_w2[oc * 144 + ic * 9];
            #pragma unroll
            for (int ky = 0; ky < 3; ky++) {
                float in[12];
                #pragma unroll
                for (int j = 0; j < 12; j++) in[j] = pin[(y + ky) * 12 + j];
                #pragma unroll
                for (int kx = 0; kx < 3; kx++) {
                    float w = pw[ky * 3 + kx];
                    #pragma unroll
                    for (int xo = 0; xo < 10; xo++)
                        acc[xo] += in[xo + kx] * w;
                }
            }
        }
        #pragma unroll
        for (int xo = 0; xo < 10; xo++)
            s_out[oc * 100 + y * 10 + xo] = fmaxf(acc[xo], 0.0f);
    }
    __syncthreads();

    // coalesced copy-out of h
    float* ho = g_h + (size_t)b * DIN;
    for (int i = tid; i < DIN; i += 320) ho[i] = s_out[i];

    // ---- fused gate: h is already in smem ----
    {
        float s[5] = {0.f, 0.f, 0.f, 0.f, 0.f};
        for (int i = tid; i < DIN; i += 320) {
            float hv = s_out[i];
            const float* g = gw + (size_t)i * 5;
            #pragma unroll
            for (int e = 0; e < 5; e++) s[e] += hv * __ldg(g + e);
        }
        #pragma unroll
        for (int off = 16; off; off >>= 1)
            #pragma unroll
            for (int e = 0; e < 5; e++)
                s[e] += __shfl_down_sync(0xffffffffu, s[e], off);
        int w = tid >> 5, lane = tid & 31;
        if (lane == 0)
            #pragma unroll
            for (int e = 0; e < 5; e++) s_red[w][e] = s[e];
        __syncthreads();
        if (tid == 0) {
            float l[5], pr[5];
            #pragma unroll
            for (int e = 0; e < 5; e++) {
                float t = gb[e];
                #pragma unroll
                for (int ww = 0; ww < 10; ww++) t += s_red[ww][e];
                l[e] = t;
            }
            float mx = l[0];
            #pragma unroll
            for (int e = 1; e < 5; e++) mx = fmaxf(mx, l[e]);
            float sum = 0.f;
            #pragma unroll
            for (int e = 0; e < 5; e++) { pr[e] = expf(l[e] - mx); sum += pr[e]; }
            float inv = 1.0f / sum;
            #pragma unroll
            for (int e = 0; e < 5; e++) pr[e] *= inv;

            bool sel[5] = {false, false, false, false, false};
            float s3sum = 0.f;
            for (int t = 0; t < 3; t++) {          // argmax, lowest index on ties
                int bi = -1; float bv = -1.f;
                #pragma unroll
                for (int e = 0; e < 5; e++)
                    if (!sel[e] && pr[e] > bv) { bv = pr[e]; bi = e; }
                sel[bi] = true; s3sum += bv;
            }
            float rinv = 1.0f / s3sum;
            #pragma unroll
            for (int e = 0; e < 5; e++)
                g_wf[(size_t)b * 5 + e] = sel[e] ? pr[e] * rinv : 0.0f;
        }
    }
}

// ============================================================================
// Kernel C: h1 = tanh(h @ e1_w[e] + e1_b[e])   (f32x2 SGEMM, the hot kernel)
// M=8192, N=128/expert, K=3200.  BM=64, BN=128, BK=32, 256 threads.
// A tile stored in smem PRE-DUPLICATED as (a,a) f32x2 pairs so the packed
// operand loads straight via LDS.128 — no scalar LDS, no mov.b64 packs.
// Per 2 k-steps: 32 FFMA2 + 8 LDS.128 = 80% FFMA2 issue efficiency.
// ============================================================================
#define BM 64
#define BN 128
#define BK 32
#define ASTRD 68   // floats per sAd row: 32 dup-pairs (64 floats) + 4 pad

__global__ __launch_bounds__(256) void e1_kernel(
    const float* __restrict__ w, const float* __restrict__ bias)
{
    __shared__ float sAd[BM * ASTRD];  // [m][k-pairs], each k -> (a,a)
    __shared__ float sB [BK * BN];     // [k][n]

    const int tid = threadIdx.x;
    const int e   = blockIdx.x;
    const int m0  = blockIdx.y * BM;
    const float* W = w + (size_t)e * DIN * DH;

    const int tm = tid >> 4;     // 0..15 -> rows tm*4..+3
    const int tn = tid & 15;     // 0..15 -> cols tn*8..+7

    unsigned long long acc[4][4];
    #pragma unroll
    for (int i = 0; i < 4; i++)
        #pragma unroll
        for (int j = 0; j < 4; j++) acc[i][j] = 0ull;

    const int a_row = tid >> 3;  // 0..31 (and +32)
    const int a_c4  = tid & 7;   // 0..7
    const int b_k0  = tid >> 5;  // 0..7 (and +8,+16,+24)
    const int b_c4  = tid & 31;  // 0..31

    for (int kk = 0; kk < DIN; kk += BK) {
        __syncthreads();
        // A tile: 64x32, stored duplicated: sAd[row][2k..2k+1] = (a_k, a_k)
        {
            float4 v0 = *(const float4*)&g_h[(size_t)(m0 + a_row) * DIN + kk + a_c4 * 4];
            float4 v1 = *(const float4*)&g_h[(size_t)(m0 + a_row + 32) * DIN + kk + a_c4 * 4];
            float* d0 = &sAd[a_row * ASTRD + a_c4 * 8];
            ((float4*)d0)[0] = make_float4(v0.x, v0.x, v0.y, v0.y);
            ((float4*)d0)[1] = make_float4(v0.z, v0.z, v0.w, v0.w);
            float* d1 = &sAd[(a_row + 32) * ASTRD + a_c4 * 8];
            ((float4*)d1)[0] = make_float4(v1.x, v1.x, v1.y, v1.y);
            ((float4*)d1)[1] = make_float4(v1.z, v1.z, v1.w, v1.w);
        }
        // B tile: 32x128, [k][n]
        #pragma unroll
        for (int i = 0; i < 4; i++) {
            int krow = b_k0 + i * 8;
            float4 v = *(const float4*)&W[(size_t)(kk + krow) * DH + b_c4 * 4];
            *(float4*)&sB[krow * BN + b_c4 * 4] = v;
        }
        __syncthreads();

        #pragma unroll 8
        for (int k = 0; k < BK; k += 2) {
            ulonglong2 b00 = *(const ulonglong2*)&sB[k * BN + tn * 8];       // n0n1,n2n3 @k
            ulonglong2 b01 = *(const ulonglong2*)&sB[k * BN + tn * 8 + 4];   // n4n5,n6n7 @k
            ulonglong2 b10 = *(const ulonglong2*)&sB[(k + 1) * BN + tn * 8];
            ulonglong2 b11 = *(const ulonglong2*)&sB[(k + 1) * BN + tn * 8 + 4];
            #pragma unroll
            for (int i = 0; i < 4; i++) {
                ulonglong2 a = *(const ulonglong2*)&sAd[(tm * 4 + i) * ASTRD + k * 2];
                fma2(acc[i][0], a.x, b00.x);
                fma2(acc[i][1], a.x, b00.y);
                fma2(acc[i][2], a.x, b01.x);
                fma2(acc[i][3], a.x, b01.y);
                fma2(acc[i][0], a.y, b10.x);
                fma2(acc[i][1], a.y, b10.y);
                fma2(acc[i][2], a.y, b11.x);
                fma2(acc[i][3], a.y, b11.y);
            }
        }
    }

    // epilogue: +bias, tanh, store h1[b][e*128 + n]
    #pragma unroll
    for (int i = 0; i < 4; i++) {
        int row = m0 + tm * 4 + i;
        float o[8];
        #pragma unroll
        for (int j = 0; j < 4; j++) {
            float2 c = up2(acc[i][j]);
            int n = tn * 8 + 2 * j;
            o[2 * j]     = tanhf(c.x + bias[e * DH + n]);
            o[2 * j + 1] = tanhf(c.y + bias[e * DH + n + 1]);
        }
        float4* dst = (float4*)&g_h1[(size_t)row * (NE * DH) + e * DH + tn * 8];
        dst[0] = make_float4(o[0], o[1], o[2], o[3]);
        dst[1] = make_float4(o[4], o[5], o[6], o[7]);
    }
}

// ============================================================================
// Kernel D: per 32-row tile: for each expert e, h2 = tanh(h1_e @ e2_w[e] + b),
// moe += w_full[:,e] * h2; then logits = moe@sm_w+sm_b, softmax -> out.
// ============================================================================
#define SAS 132

__global__ __launch_bounds__(256) void e2_head_kernel(
    const float* __restrict__ w2e, const float* __restrict__ b2e,
    const float* __restrict__ smw, const float* __restrict__ smb,
    float* __restrict__ out)
{
    extern __shared__ float dsm[];
    float* sW    = dsm;                    // 128*128 = 16384
    float* sA    = dsm + 16384;            // 32*SAS  = 4224
    float* s_smw = dsm + 16384 + 4224;     // 128*10  = 1280
    float* s_wf  = s_smw + 1280;           // 32*5    = 160

    const int tid = threadIdx.x;
    const int m0  = blockIdx.x * 32;
    const int tm  = tid >> 4;   // 0..15 -> rows tm*2..+1
    const int tn  = tid & 15;   // 0..15 -> cols tn*8..+7

    for (int i = tid; i < DH * 10; i += 256) s_smw[i] = smw[i];
    for (int i = tid; i < 160;     i += 256) s_wf[i]  = g_wf[(size_t)m0 * 5 + i];

    float moe[2][8];
    #pragma unroll
    for (int i = 0; i < 2; i++)
        #pragma unroll
        for (int j = 0; j < 8; j++) moe[i][j] = 0.f;

    for (int e = 0; e < NE; e++) {
        __syncthreads();
        for (int i = tid; i < (DH * DH) / 4; i += 256)
            ((float4*)sW)[i] = ((const float4*)(w2e + (size_t)e * DH * DH))[i];
        for (int i = tid; i < (32 * DH) / 4; i += 256) {
            int r = i / (DH / 4), c4 = i % (DH / 4);
            float4 v = *(const float4*)&g_h1[(size_t)(m0 + r) * (NE * DH) + e * DH + c4 * 4];
            *(float4*)&sA[r * SAS + c4 * 4] = v;
        }
        __syncthreads();

        float acc[2][8];
        #pragma unroll
        for (int i = 0; i < 2; i++)
            #pragma unroll
            for (int j = 0; j < 8; j++) acc[i][j] = 0.f;

        #pragma unroll 4
        for (int k = 0; k < DH; k++) {
            float a0 = sA[(tm * 2) * SAS + k];
            float a1 = sA[(tm * 2 + 1) * SAS + k];
            float4 bv0 = *(const float4*)&sW[k * DH + tn * 8];
            float4 bv1 = *(const float4*)&sW[k * DH + tn * 8 + 4];
            float bv[8] = {bv0.x, bv0.y, bv0.z, bv0.w, bv1.x, bv1.y, bv1.z, bv1.w};
            #pragma unroll
            for (int j = 0; j < 8; j++) {
                acc[0][j] += a0 * bv[j];
                acc[1][j] += a1 * bv[j];
            }
        }
        #pragma unroll
        for (int i = 0; i < 2; i++) {
            float wfe = s_wf[(tm * 2 + i) * 5 + e];
            #pragma unroll
            for (int j = 0; j < 8; j++)
                moe[i][j] += wfe * tanhf(acc[i][j] + b2e[e * DH + tn * 8 + j]);
        }
    }
    __syncthreads();
    #pragma unroll
    for (int i = 0; i < 2; i++)
        #pragma unroll
        for (int j = 0; j < 8; j++)
            sA[(tm * 2 + i) * SAS + tn * 8 + j] = moe[i][j];
    __syncthreads();

    if (tid < 32) {
        int r = tid;
        float lg[10];
        #pragma unroll
        for (int c = 0; c < 10; c++) lg[c] = smb[c];
        for (int k = 0; k < DH; k++) {
            float m = sA[r * SAS + k];
            #pragma unroll
            for (int c = 0; c < 10; c++) lg[c] += m * s_smw[k * 10 + c];
        }
        float mx = lg[0];
        #pragma unroll
        for (int c = 1; c < 10; c++) mx = fmaxf(mx, lg[c]);
        float ex[10], s = 0.f;
        #pragma unroll
        for (int c = 0; c < 10; c++) { ex[c] = expf(lg[c] - mx); s += ex[c]; }
        float inv = 1.0f / s;
        #pragma unroll
        for (int c = 0; c < 10; c++)
            out[(size_t)(m0 + r) * 10 + c] = ex[c] * inv;
    }
}

// ============================================================================
// launch
// ============================================================================
extern "C" void kernel_launch(void* const* d_in, const int* in_sizes, int n_in,
                              void* d_out, int out_size)
{
    (void)in_sizes; (void)n_in; (void)out_size;
    const float* x   = (const float*)d_in[0];
    const float* c1w = (const float*)d_in[1];
    const float* c1b = (const float*)d_in[2];
    const float* c2w = (const float*)d_in[3];
    const float* c2b = (const float*)d_in[4];
    const float* gw  = (const float*)d_in[5];
    const float* gb  = (const float*)d_in[6];
    const float* e1w = (const float*)d_in[7];
    const float* e1b = (const float*)d_in[8];
    const float* e2w = (const float*)d_in[9];
    const float* e2b = (const float*)d_in[10];
    const float* smw = (const float*)d_in[11];
    const float* smb = (const float*)d_in[12];
    float* out = (float*)d_out;

    const int dsmem = (16384 + 32 * SAS + 1280 + 160) * 4;
    cudaFuncSetAttribute(e2_head_kernel,
                         cudaFuncAttributeMaxDynamicSharedMemorySize, dsmem);

    conv_kernel<<<BATCH, 320>>>(x, c1w, c1b, c2w, c2b, gw, gb);
    e1_kernel<<<dim3(NE, BATCH / BM), 256>>>(e1w, e1b);
    e2_head_kernel<<<BATCH / 32, 256, dsmem>>>(e2w, e2b, smw, smb, out);
}

// round 16
// speedup vs baseline: 1.1150x; 1.1150x over previous
#include <cuda_runtime.h>
#include <math.h>

#define BATCH 8192
#define DIN   3200
#define DH    128
#define NE    5

// ---------------- scratch (static device globals: allocation-free) ----------
__device__ float g_h [BATCH * DIN];        // conv features      [B,3200]
__device__ float g_h1[BATCH * NE * DH];    // tanh(e1) outputs   [B,640]
__device__ float g_wf[BATCH * NE];         // sparse top-3 gate  [B,5]

// ---------------- f32x2 helpers (IEEE-identical to two fmaf) ----------------
__device__ __forceinline__ unsigned long long pk2(float lo, float hi) {
    unsigned long long r;
    asm("mov.b64 %0, {%1,%2};" : "=l"(r) : "f"(lo), "f"(hi));
    return r;
}
__device__ __forceinline__ void fma2(unsigned long long& d,
                                     unsigned long long a,
                                     unsigned long long b) {
    asm("fma.rn.f32x2 %0, %1, %2, %0;" : "+l"(d) : "l"(a), "l"(b));
}
__device__ __forceinline__ float2 up2(unsigned long long v) {
    float2 f;
    asm("mov.b64 {%0,%1}, %2;" : "=f"(f.x), "=f"(f.y) : "l"(v));
    return f;
}

// ============================================================================
// Kernel A: conv1(5x5,16)+ReLU -> maxpool2 -> conv2(3x3,32)+ReLU -> g_h
//           + FUSED gate: softmax(h@gate_w+gate_b), top-3, renorm -> g_wf
// One block per image, 320 threads. Register-blocked to cut LDS/FMA
// (kernel is shared-memory-wavefront bound: L1 was 95.3%).
// ============================================================================
__global__ __launch_bounds__(320) void conv_kernel(
    const float* __restrict__ x,
    const float* __restrict__ w1, const float* __restrict__ b1,
    const float* __restrict__ w2, const float* __restrict__ b2,
    const float* __restrict__ gw, const float* __restrict__ gb)
{
    __shared__ float s_img [784];
    __shared__ float s_w1  [400];
    __shared__ float s_b1  [16];
    __shared__ float s_pool[2304];   // [16][12][12]
    __shared__ float s_w2  [4608];   // [32][16][9]
    __shared__ float s_b2  [32];
    __shared__ float s_out [3200];
    __shared__ float s_red [10][5];

    const int tid = threadIdx.x;
    const int b   = blockIdx.x;

    const float* xi = x + (size_t)b * 784;
    for (int i = tid; i < 784;  i += 320) s_img[i] = xi[i];
    for (int i = tid; i < 400;  i += 320) s_w1[i]  = w1[i];
    if (tid < 16) s_b1[tid] = b1[tid];
    for (int i = tid; i < 4608; i += 320) s_w2[i]  = w2[i];
    if (tid < 32) s_b2[tid] = b2[tid];
    __syncthreads();

    // conv1 + relu + maxpool, 2x2-pooled-block register blocking:
    // task = (oc, 2x2 pooled block) -> 4x4 conv outputs from an 8-row window.
    // 25 weights held in registers; 64 row loads + 25 weight loads per 400 FMA.
    for (int idx = tid; idx < 576; idx += 320) {
        int oc = idx / 36, r = idx % 36;
        int by = r / 6,   bx = r % 6;
        int iy = 4 * by,  ix = 4 * bx;

        float wreg[25];
        #pragma unroll
        for (int i = 0; i < 25; i++) wreg[i] = s_w1[oc * 25 + i];

        float bb = s_b1[oc];
        float acc[4][4];
        #pragma unroll
        for (int cy = 0; cy < 4; cy++)
            #pragma unroll
            for (int ox = 0; ox < 4; ox++) acc[cy][ox] = bb;

        #pragma unroll
        for (int ry = 0; ry < 8; ry++) {
            float row[8];
            #pragma unroll
            for (int rx = 0; rx < 8; rx++)
                row[rx] = s_img[(iy + ry) * 28 + ix + rx];
            #pragma unroll
            for (int cy = 0; cy < 4; cy++) {
                if (cy <= ry && ry <= cy + 4) {      // folds at compile time
                    int kyw = ry - cy;
                    #pragma unroll
                    for (int kx = 0; kx < 5; kx++) {
                        float w = wreg[kyw * 5 + kx];
                        #pragma unroll
                        for (int ox = 0; ox < 4; ox++)
                            acc[cy][ox] += row[ox + kx] * w;
                    }
                }
            }
        }
        // 2x2 maxpool over the 4x4 conv outputs, then relu
        #pragma unroll
        for (int dy = 0; dy < 2; dy++)
            #pragma unroll
            for (int dx = 0; dx < 2; dx++) {
                float m = fmaxf(fmaxf(acc[2*dy][2*dx],     acc[2*dy][2*dx+1]),
                                fmaxf(acc[2*dy+1][2*dx],   acc[2*dy+1][2*dx+1]));
                s_pool[oc * 144 + (2*by + dy) * 12 + (2*bx + dx)] = fmaxf(m, 0.0f);
            }
    }
    __syncthreads();

    // conv2 + relu: thread = (oc-pair, out-row y); input rows loaded once per
    // ic serve BOTH output channels (36 in + 18 w loads per 180 FMA).
    if (tid < 160) {
        int ocp = tid / 10;       // 0..15 -> channels 2*ocp, 2*ocp+1
        int y   = tid % 10;
        int oc0 = 2 * ocp;

        float acc[2][10];
        float b0 = s_b2[oc0], b1v = s_b2[oc0 + 1];
        #pragma unroll
        for (int j = 0; j < 10; j++) { acc[0][j] = b0; acc[1][j] = b1v; }

        for (int ic = 0; ic < 16; ic++) {
            const float* pin = &s_pool[ic * 144];
            const float* pw0 = &s_w2[oc0 * 144 + ic * 9];
            const float* pw1 = pw0 + 144;
            #pragma unroll
            for (int ky = 0; ky < 3; ky++) {
                float in[12];
                #pragma unroll
                for (int j = 0; j < 12; j++) in[j] = pin[(y + ky) * 12 + j];
                #pragma unroll
                for (int kx = 0; kx < 3; kx++) {
                    float w0 = pw0[ky * 3 + kx];
                    float w1 = pw1[ky * 3 + kx];
                    #pragma unroll
                    for (int xo = 0; xo < 10; xo++) {
                        acc[0][xo] += in[xo + kx] * w0;
                        acc[1][xo] += in[xo + kx] * w1;
                    }
                }
            }
        }
        #pragma unroll
        for (int xo = 0; xo < 10; xo++) {
            s_out[oc0 * 100 + y * 10 + xo]         = fmaxf(acc[0][xo], 0.0f);
            s_out[(oc0 + 1) * 100 + y * 10 + xo]   = fmaxf(acc[1][xo], 0.0f);
        }
    }
    __syncthreads();

    // coalesced copy-out of h
    float* ho = g_h + (size_t)b * DIN;
    for (int i = tid; i < DIN; i += 320) ho[i] = s_out[i];

    // ---- fused gate: h is already in smem ----
    {
        float s[5] = {0.f, 0.f, 0.f, 0.f, 0.f};
        for (int i = tid; i < DIN; i += 320) {
            float hv = s_out[i];
            const float* g = gw + (size_t)i * 5;
            #pragma unroll
            for (int e = 0; e < 5; e++) s[e] += hv * __ldg(g + e);
        }
        #pragma unroll
        for (int off = 16; off; off >>= 1)
            #pragma unroll
            for (int e = 0; e < 5; e++)
                s[e] += __shfl_down_sync(0xffffffffu, s[e], off);
        int w = tid >> 5, lane = tid & 31;
        if (lane == 0)
            #pragma unroll
            for (int e = 0; e < 5; e++) s_red[w][e] = s[e];
        __syncthreads();
        if (tid == 0) {
            float l[5], pr[5];
            #pragma unroll
            for (int e = 0; e < 5; e++) {
                float t = gb[e];
                #pragma unroll
                for (int ww = 0; ww < 10; ww++) t += s_red[ww][e];
                l[e] = t;
            }
            float mx = l[0];
            #pragma unroll
            for (int e = 1; e < 5; e++) mx = fmaxf(mx, l[e]);
            float sum = 0.f;
            #pragma unroll
            for (int e = 0; e < 5; e++) { pr[e] = expf(l[e] - mx); sum += pr[e]; }
            float inv = 1.0f / sum;
            #pragma unroll
            for (int e = 0; e < 5; e++) pr[e] *= inv;

            bool sel[5] = {false, false, false, false, false};
            float s3sum = 0.f;
            for (int t = 0; t < 3; t++) {          // argmax, lowest index on ties
                int bi = -1; float bv = -1.f;
                #pragma unroll
                for (int e = 0; e < 5; e++)
                    if (!sel[e] && pr[e] > bv) { bv = pr[e]; bi = e; }
                sel[bi] = true; s3sum += bv;
            }
            float rinv = 1.0f / s3sum;
            #pragma unroll
            for (int e = 0; e < 5; e++)
                g_wf[(size_t)b * 5 + e] = sel[e] ? pr[e] * rinv : 0.0f;
        }
    }
}

// ============================================================================
// Kernel C: h1 = tanh(h @ e1_w[e] + e1_b[e])   (f32x2 SGEMM, the hot kernel)
// REVERTED to the round-14 proven version (~880us). The pre-duplicated-A
// rewrite regressed to ~1420us (register pressure from the fully-unrolled
// ulonglong2 loop + doubled A-store traffic).
// M=8192, N=128 per expert, K=3200.  BM=64, BN=128, BK=32, 256 threads,
// 4m x 8n micro-tile held as 4x4 f32x2 accumulators.
// ============================================================================
#define BM 64
#define BN 128
#define BK 32
#define ASTR 36   // sA row stride (pad keeps 16B alignment, kills conflicts)

__global__ __launch_bounds__(256) void e1_kernel(
    const float* __restrict__ w, const float* __restrict__ bias)
{
    __shared__ float sA[BM * ASTR];   // [m][k]
    __shared__ float sB[BK * BN];     // [k][n]

    const int tid = threadIdx.x;
    const int e   = blockIdx.x;
    const int m0  = blockIdx.y * BM;
    const float* W = w + (size_t)e * DIN * DH;

    const int tm = tid >> 4;     // 0..15 -> rows tm*4..+3
    const int tn = tid & 15;     // 0..15 -> cols tn*8..+7

    unsigned long long acc[4][4];
    #pragma unroll
    for (int i = 0; i < 4; i++)
        #pragma unroll
        for (int j = 0; j < 4; j++) acc[i][j] = 0ull;

    const int a_row = tid >> 3;  // 0..31 (and +32)
    const int a_c4  = tid & 7;   // 0..7
    const int b_k0  = tid >> 5;  // 0..7 (and +8,+16,+24)
    const int b_c4  = tid & 31;  // 0..31

    for (int kk = 0; kk < DIN; kk += BK) {
        __syncthreads();
        // A tile: 64x32 (2 float4 per thread), stored [m][k]
        {
            float4 v0 = *(const float4*)&g_h[(size_t)(m0 + a_row) * DIN + kk + a_c4 * 4];
            float4 v1 = *(const float4*)&g_h[(size_t)(m0 + a_row + 32) * DIN + kk + a_c4 * 4];
            *(float4*)&sA[a_row * ASTR + a_c4 * 4]        = v0;
            *(float4*)&sA[(a_row + 32) * ASTR + a_c4 * 4] = v1;
        }
        // B tile: 32x128 (4 float4 per thread), stored [k][n]
        #pragma unroll
        for (int i = 0; i < 4; i++) {
            int krow = b_k0 + i * 8;
            float4 v = *(const float4*)&W[(size_t)(kk + krow) * DH + b_c4 * 4];
            *(float4*)&sB[krow * BN + b_c4 * 4] = v;
        }
        __syncthreads();

        #pragma unroll
        for (int k = 0; k < BK; k++) {
            const float* bp = &sB[k * BN + tn * 8];
            unsigned long long b0 = *(const unsigned long long*)(bp + 0);
            unsigned long long b1 = *(const unsigned long long*)(bp + 2);
            unsigned long long b2 = *(const unsigned long long*)(bp + 4);
            unsigned long long b3 = *(const unsigned long long*)(bp + 6);
            #pragma unroll
            for (int i = 0; i < 4; i++) {
                float a = sA[(tm * 4 + i) * ASTR + k];
                unsigned long long a2 = pk2(a, a);
                fma2(acc[i][0], a2, b0);
                fma2(acc[i][1], a2, b1);
                fma2(acc[i][2], a2, b2);
                fma2(acc[i][3], a2, b3);
            }
        }
    }

    // epilogue: +bias, tanh, store h1[b][e*128 + n]
    #pragma unroll
    for (int i = 0; i < 4; i++) {
        int row = m0 + tm * 4 + i;
        float o[8];
        #pragma unroll
        for (int j = 0; j < 4; j++) {
            float2 c = up2(acc[i][j]);
            int n = tn * 8 + 2 * j;
            o[2 * j]     = tanhf(c.x + bias[e * DH + n]);
            o[2 * j + 1] = tanhf(c.y + bias[e * DH + n + 1]);
        }
        float4* dst = (float4*)&g_h1[(size_t)row * (NE * DH) + e * DH + tn * 8];
        dst[0] = make_float4(o[0], o[1], o[2], o[3]);
        dst[1] = make_float4(o[4], o[5], o[6], o[7]);
    }
}

// ============================================================================
// Kernel D: per 32-row tile: for each expert e, h2 = tanh(h1_e @ e2_w[e] + b),
// moe += w_full[:,e] * h2; then logits = moe@sm_w+sm_b, softmax -> out.
// ============================================================================
#define SAS 132

__global__ __launch_bounds__(256) void e2_head_kernel(
    const float* __restrict__ w2e, const float* __restrict__ b2e,
    const float* __restrict__ smw, const float* __restrict__ smb,
    float* __restrict__ out)
{
    extern __shared__ float dsm[];
    float* sW    = dsm;                    // 128*128 = 16384
    float* sA    = dsm + 16384;            // 32*SAS  = 4224
    float* s_smw = dsm + 16384 + 4224;     // 128*10  = 1280
    float* s_wf  = s_smw + 1280;           // 32*5    = 160

    const int tid = threadIdx.x;
    const int m0  = blockIdx.x * 32;
    const int tm  = tid >> 4;   // 0..15 -> rows tm*2..+1
    const int tn  = tid & 15;   // 0..15 -> cols tn*8..+7

    for (int i = tid; i < DH * 10; i += 256) s_smw[i] = smw[i];
    for (int i = tid; i < 160;     i += 256) s_wf[i]  = g_wf[(size_t)m0 * 5 + i];

    float moe[2][8];
    #pragma unroll
    for (int i = 0; i < 2; i++)
        #pragma unroll
        for (int j = 0; j < 8; j++) moe[i][j] = 0.f;

    for (int e = 0; e < NE; e++) {
        __syncthreads();
        for (int i = tid; i < (DH * DH) / 4; i += 256)
            ((float4*)sW)[i] = ((const float4*)(w2e + (size_t)e * DH * DH))[i];
        for (int i = tid; i < (32 * DH) / 4; i += 256) {
            int r = i / (DH / 4), c4 = i % (DH / 4);
            float4 v = *(const float4*)&g_h1[(size_t)(m0 + r) * (NE * DH) + e * DH + c4 * 4];
            *(float4*)&sA[r * SAS + c4 * 4] = v;
        }
        __syncthreads();

        float acc[2][8];
        #pragma unroll
        for (int i = 0; i < 2; i++)
            #pragma unroll
            for (int j = 0; j < 8; j++) acc[i][j] = 0.f;

        #pragma unroll 4
        for (int k = 0; k < DH; k++) {
            float a0 = sA[(tm * 2) * SAS + k];
            float a1 = sA[(tm * 2 + 1) * SAS + k];
            float4 bv0 = *(const float4*)&sW[k * DH + tn * 8];
            float4 bv1 = *(const float4*)&sW[k * DH + tn * 8 + 4];
            float bv[8] = {bv0.x, bv0.y, bv0.z, bv0.w, bv1.x, bv1.y, bv1.z, bv1.w};
            #pragma unroll
            for (int j = 0; j < 8; j++) {
                acc[0][j] += a0 * bv[j];
                acc[1][j] += a1 * bv[j];
            }
        }
        #pragma unroll
        for (int i = 0; i < 2; i++) {
            float wfe = s_wf[(tm * 2 + i) * 5 + e];
            #pragma unroll
            for (int j = 0; j < 8; j++)
                moe[i][j] += wfe * tanhf(acc[i][j] + b2e[e * DH + tn * 8 + j]);
        }
    }
    __syncthreads();
    #pragma unroll
    for (int i = 0; i < 2; i++)
        #pragma unroll
        for (int j = 0; j < 8; j++)
            sA[(tm * 2 + i) * SAS + tn * 8 + j] = moe[i][j];
    __syncthreads();

    if (tid < 32) {
        int r = tid;
        float lg[10];
        #pragma unroll
        for (int c = 0; c < 10; c++) lg[c] = smb[c];
        for (int k = 0; k < DH; k++) {
            float m = sA[r * SAS + k];
            #pragma unroll
            for (int c = 0; c < 10; c++) lg[c] += m * s_smw[k * 10 + c];
        }
        float mx = lg[0];
        #pragma unroll
        for (int c = 1; c < 10; c++) mx = fmaxf(mx, lg[c]);
        float ex[10], s = 0.f;
        #pragma unroll
        for (int c = 0; c < 10; c++) { ex[c] = expf(lg[c] - mx); s += ex[c]; }
        float inv = 1.0f / s;
        #pragma unroll
        for (int c = 0; c < 10; c++)
            out[(size_t)(m0 + r) * 10 + c] = ex[c] * inv;
    }
}

// ============================================================================
// launch
// ============================================================================
extern "C" void kernel_launch(void* const* d_in, const int* in_sizes, int n_in,
                              void* d_out, int out_size)
{
    (void)in_sizes; (void)n_in; (void)out_size;
    const float* x   = (const float*)d_in[0];
    const float* c1w = (const float*)d_in[1];
    const float* c1b = (const float*)d_in[2];
    const float* c2w = (const float*)d_in[3];
    const float* c2b = (const float*)d_in[4];
    const float* gw  = (const float*)d_in[5];
    const float* gb  = (const float*)d_in[6];
    const float* e1w = (const float*)d_in[7];
    const float* e1b = (const float*)d_in[8];
    const float* e2w = (const float*)d_in[9];
    const float* e2b = (const float*)d_in[10];
    const float* smw = (const float*)d_in[11];
    const float* smb = (const float*)d_in[12];
    float* out = (float*)d_out;

    const int dsmem = (16384 + 32 * SAS + 1280 + 160) * 4;
    cudaFuncSetAttribute(e2_head_kernel,
                         cudaFuncAttributeMaxDynamicSharedMemorySize, dsmem);

    conv_kernel<<<BATCH, 320>>>(x, c1w, c1b, c2w, c2b, gw, gb);
    e1_kernel<<<dim3(NE, BATCH / BM), 256>>>(e1w, e1b);
    e2_head_kernel<<<BATCH / 32, 256, dsmem>>>(e2w, e2b, smw, smb, out);
}

// round 17
// speedup vs baseline: 1.1162x; 1.0010x over previous
#include <cuda_runtime.h>
#include <math.h>

#define BATCH 8192
#define DIN   3200
#define DH    128
#define NE    5

// ---------------- scratch (static device globals: allocation-free) ----------
__device__ float g_h [BATCH * DIN];        // conv features      [B,3200]
__device__ float g_h1[BATCH * NE * DH];    // tanh(e1) outputs   [B,640]
__device__ float g_wf[BATCH * NE];         // sparse top-3 gate  [B,5]

// ---------------- f32x2 helpers (IEEE-identical to two fmaf) ----------------
__device__ __forceinline__ unsigned long long pk2(float lo, float hi) {
    unsigned long long r;
    asm("mov.b64 %0, {%1,%2};" : "=l"(r) : "f"(lo), "f"(hi));
    return r;
}
__device__ __forceinline__ void fma2(unsigned long long& d,
                                     unsigned long long a,
                                     unsigned long long b) {
    asm("fma.rn.f32x2 %0, %1, %2, %0;" : "+l"(d) : "l"(a), "l"(b));
}
__device__ __forceinline__ float2 up2(unsigned long long v) {
    float2 f;
    asm("mov.b64 {%0,%1}, %2;" : "=f"(f.x), "=f"(f.y) : "l"(v));
    return f;
}

// ============================================================================
// Kernel A: conv1(5x5,16)+ReLU -> maxpool2 -> conv2(3x3,32)+ReLU -> g_h
//           + FUSED gate: softmax(h@gate_w+gate_b), top-3, renorm -> g_wf
// One block per image, 320 threads. Register-blocked to cut LDS/FMA
// (kernel is shared-memory-wavefront bound: L1 was 95.3%).
// ============================================================================
__global__ __launch_bounds__(320) void conv_kernel(
    const float* __restrict__ x,
    const float* __restrict__ w1, const float* __restrict__ b1,
    const float* __restrict__ w2, const float* __restrict__ b2,
    const float* __restrict__ gw, const float* __restrict__ gb)
{
    __shared__ float s_img [784];
    __shared__ float s_w1  [400];
    __shared__ float s_b1  [16];
    __shared__ float s_pool[2304];   // [16][12][12]
    __shared__ float s_w2  [4608];   // [32][16][9]
    __shared__ float s_b2  [32];
    __shared__ float s_out [3200];
    __shared__ float s_red [10][5];

    const int tid = threadIdx.x;
    const int b   = blockIdx.x;

    const float* xi = x + (size_t)b * 784;
    for (int i = tid; i < 784;  i += 320) s_img[i] = xi[i];
    for (int i = tid; i < 400;  i += 320) s_w1[i]  = w1[i];
    if (tid < 16) s_b1[tid] = b1[tid];
    for (int i = tid; i < 4608; i += 320) s_w2[i]  = w2[i];
    if (tid < 32) s_b2[tid] = b2[tid];
    __syncthreads();

    // conv1 + relu + maxpool, 2x2-pooled-block register blocking:
    // task = (oc, 2x2 pooled block) -> 4x4 conv outputs from an 8-row window.
    // 25 weights held in registers; 64 row loads + 25 weight loads per 400 FMA.
    for (int idx = tid; idx < 576; idx += 320) {
        int oc = idx / 36, r = idx % 36;
        int by = r / 6,   bx = r % 6;
        int iy = 4 * by,  ix = 4 * bx;

        float wreg[25];
        #pragma unroll
        for (int i = 0; i < 25; i++) wreg[i] = s_w1[oc * 25 + i];

        float bb = s_b1[oc];
        float acc[4][4];
        #pragma unroll
        for (int cy = 0; cy < 4; cy++)
            #pragma unroll
            for (int ox = 0; ox < 4; ox++) acc[cy][ox] = bb;

        #pragma unroll
        for (int ry = 0; ry < 8; ry++) {
            float row[8];
            #pragma unroll
            for (int rx = 0; rx < 8; rx++)
                row[rx] = s_img[(iy + ry) * 28 + ix + rx];
            #pragma unroll
            for (int cy = 0; cy < 4; cy++) {
                if (cy <= ry && ry <= cy + 4) {      // folds at compile time
                    int kyw = ry - cy;
                    #pragma unroll
                    for (int kx = 0; kx < 5; kx++) {
                        float w = wreg[kyw * 5 + kx];
                        #pragma unroll
                        for (int ox = 0; ox < 4; ox++)
                            acc[cy][ox] += row[ox + kx] * w;
                    }
                }
            }
        }
        // 2x2 maxpool over the 4x4 conv outputs, then relu
        #pragma unroll
        for (int dy = 0; dy < 2; dy++)
            #pragma unroll
            for (int dx = 0; dx < 2; dx++) {
                float m = fmaxf(fmaxf(acc[2*dy][2*dx],     acc[2*dy][2*dx+1]),
                                fmaxf(acc[2*dy+1][2*dx],   acc[2*dy+1][2*dx+1]));
                s_pool[oc * 144 + (2*by + dy) * 12 + (2*bx + dx)] = fmaxf(m, 0.0f);
            }
    }
    __syncthreads();

    // conv2 + relu: thread = (oc-pair, out-row y); input rows loaded once per
    // ic serve BOTH output channels (36 in + 18 w loads per 180 FMA).
    if (tid < 160) {
        int ocp = tid / 10;       // 0..15 -> channels 2*ocp, 2*ocp+1
        int y   = tid % 10;
        int oc0 = 2 * ocp;

        float acc[2][10];
        float b0 = s_b2[oc0], b1v = s_b2[oc0 + 1];
        #pragma unroll
        for (int j = 0; j < 10; j++) { acc[0][j] = b0; acc[1][j] = b1v; }

        for (int ic = 0; ic < 16; ic++) {
            const float* pin = &s_pool[ic * 144];
            const float* pw0 = &s_w2[oc0 * 144 + ic * 9];
            const float* pw1 = pw0 + 144;
            #pragma unroll
            for (int ky = 0; ky < 3; ky++) {
                float in[12];
                #pragma unroll
                for (int j = 0; j < 12; j++) in[j] = pin[(y + ky) * 12 + j];
                #pragma unroll
                for (int kx = 0; kx < 3; kx++) {
                    float w0 = pw0[ky * 3 + kx];
                    float w1 = pw1[ky * 3 + kx];
                    #pragma unroll
                    for (int xo = 0; xo < 10; xo++) {
                        acc[0][xo] += in[xo + kx] * w0;
                        acc[1][xo] += in[xo + kx] * w1;
                    }
                }
            }
        }
        #pragma unroll
        for (int xo = 0; xo < 10; xo++) {
            s_out[oc0 * 100 + y * 10 + xo]         = fmaxf(acc[0][xo], 0.0f);
            s_out[(oc0 + 1) * 100 + y * 10 + xo]   = fmaxf(acc[1][xo], 0.0f);
        }
    }
    __syncthreads();

    // coalesced copy-out of h
    float* ho = g_h + (size_t)b * DIN;
    for (int i = tid; i < DIN; i += 320) ho[i] = s_out[i];

    // ---- fused gate: h is already in smem ----
    {
        float s[5] = {0.f, 0.f, 0.f, 0.f, 0.f};
        for (int i = tid; i < DIN; i += 320) {
            float hv = s_out[i];
            const float* g = gw + (size_t)i * 5;
            #pragma unroll
            for (int e = 0; e < 5; e++) s[e] += hv * __ldg(g + e);
        }
        #pragma unroll
        for (int off = 16; off; off >>= 1)
            #pragma unroll
            for (int e = 0; e < 5; e++)
                s[e] += __shfl_down_sync(0xffffffffu, s[e], off);
        int w = tid >> 5, lane = tid & 31;
        if (lane == 0)
            #pragma unroll
            for (int e = 0; e < 5; e++) s_red[w][e] = s[e];
        __syncthreads();
        if (tid == 0) {
            float l[5], pr[5];
            #pragma unroll
            for (int e = 0; e < 5; e++) {
                float t = gb[e];
                #pragma unroll
                for (int ww = 0; ww < 10; ww++) t += s_red[ww][e];
                l[e] = t;
            }
            float mx = l[0];
            #pragma unroll
            for (int e = 1; e < 5; e++) mx = fmaxf(mx, l[e]);
            float sum = 0.f;
            #pragma unroll
            for (int e = 0; e < 5; e++) { pr[e] = expf(l[e] - mx); sum += pr[e]; }
            float inv = 1.0f / sum;
            #pragma unroll
            for (int e = 0; e < 5; e++) pr[e] *= inv;

            bool sel[5] = {false, false, false, false, false};
            float s3sum = 0.f;
            for (int t = 0; t < 3; t++) {          // argmax, lowest index on ties
                int bi = -1; float bv = -1.f;
                #pragma unroll
                for (int e = 0; e < 5; e++)
                    if (!sel[e] && pr[e] > bv) { bv = pr[e]; bi = e; }
                sel[bi] = true; s3sum += bv;
            }
            float rinv = 1.0f / s3sum;
            #pragma unroll
            for (int e = 0; e < 5; e++)
                g_wf[(size_t)b * 5 + e] = sel[e] ? pr[e] * rinv : 0.0f;
        }
    }
}

// ============================================================================
// Kernel C: h1 = tanh(h @ e1_w[e] + e1_b[e])   (f32x2 SGEMM, the hot kernel)
// REVERTED to the round-14 proven version (~880us). The pre-duplicated-A
// rewrite regressed to ~1420us (register pressure from the fully-unrolled
// ulonglong2 loop + doubled A-store traffic).
// M=8192, N=128 per expert, K=3200.  BM=64, BN=128, BK=32, 256 threads,
// 4m x 8n micro-tile held as 4x4 f32x2 accumulators.
// ============================================================================
#define BM 64
#define BN 128
#define BK 32
#define ASTR 36   // sA row stride (pad keeps 16B alignment, kills conflicts)

__global__ __launch_bounds__(256) void e1_kernel(
    const float* __restrict__ w, const float* __restrict__ bias)
{
    __shared__ float sA[BM * ASTR];   // [m][k]
    __shared__ float sB[BK * BN];     // [k][n]

    const int tid = threadIdx.x;
    const int e   = blockIdx.x;
    const int m0  = blockIdx.y * BM;
    const float* W = w + (size_t)e * DIN * DH;

    const int tm = tid >> 4;     // 0..15 -> rows tm*4..+3
    const int tn = tid & 15;     // 0..15 -> cols tn*8..+7

    unsigned long long acc[4][4];
    #pragma unroll
    for (int i = 0; i < 4; i++)
        #pragma unroll
        for (int j = 0; j < 4; j++) acc[i][j] = 0ull;

    const int a_row = tid >> 3;  // 0..31 (and +32)
    const int a_c4  = tid & 7;   // 0..7
    const int b_k0  = tid >> 5;  // 0..7 (and +8,+16,+24)
    const int b_c4  = tid & 31;  // 0..31

    for (int kk = 0; kk < DIN; kk += BK) {
        __syncthreads();
        // A tile: 64x32 (2 float4 per thread), stored [m][k]
        {
            float4 v0 = *(const float4*)&g_h[(size_t)(m0 + a_row) * DIN + kk + a_c4 * 4];
            float4 v1 = *(const float4*)&g_h[(size_t)(m0 + a_row + 32) * DIN + kk + a_c4 * 4];
            *(float4*)&sA[a_row * ASTR + a_c4 * 4]        = v0;
            *(float4*)&sA[(a_row + 32) * ASTR + a_c4 * 4] = v1;
        }
        // B tile: 32x128 (4 float4 per thread), stored [k][n]
        #pragma unroll
        for (int i = 0; i < 4; i++) {
            int krow = b_k0 + i * 8;
            float4 v = *(const float4*)&W[(size_t)(kk + krow) * DH + b_c4 * 4];
            *(float4*)&sB[krow * BN + b_c4 * 4] = v;
        }
        __syncthreads();

        #pragma unroll
        for (int k = 0; k < BK; k++) {
            const float* bp = &sB[k * BN + tn * 8];
            unsigned long long b0 = *(const unsigned long long*)(bp + 0);
            unsigned long long b1 = *(const unsigned long long*)(bp + 2);
            unsigned long long b2 = *(const unsigned long long*)(bp + 4);
            unsigned long long b3 = *(const unsigned long long*)(bp + 6);
            #pragma unroll
            for (int i = 0; i < 4; i++) {
                float a = sA[(tm * 4 + i) * ASTR + k];
                unsigned long long a2 = pk2(a, a);
                fma2(acc[i][0], a2, b0);
                fma2(acc[i][1], a2, b1);
                fma2(acc[i][2], a2, b2);
                fma2(acc[i][3], a2, b3);
            }
        }
    }

    // epilogue: +bias, tanh, store h1[b][e*128 + n]
    #pragma unroll
    for (int i = 0; i < 4; i++) {
        int row = m0 + tm * 4 + i;
        float o[8];
        #pragma unroll
        for (int j = 0; j < 4; j++) {
            float2 c = up2(acc[i][j]);
            int n = tn * 8 + 2 * j;
            o[2 * j]     = tanhf(c.x + bias[e * DH + n]);
            o[2 * j + 1] = tanhf(c.y + bias[e * DH + n + 1]);
        }
        float4* dst = (float4*)&g_h1[(size_t)row * (NE * DH) + e * DH + tn * 8];
        dst[0] = make_float4(o[0], o[1], o[2], o[3]);
        dst[1] = make_float4(o[4], o[5], o[6], o[7]);
    }
}

// ============================================================================
// Kernel D: per 32-row tile: for each expert e, h2 = tanh(h1_e @ e2_w[e] + b),
// moe += w_full[:,e] * h2; then logits = moe@sm_w+sm_b, softmax -> out.
// ============================================================================
#define SAS 132

__global__ __launch_bounds__(256) void e2_head_kernel(
    const float* __restrict__ w2e, const float* __restrict__ b2e,
    const float* __restrict__ smw, const float* __restrict__ smb,
    float* __restrict__ out)
{
    extern __shared__ float dsm[];
    float* sW    = dsm;                    // 128*128 = 16384
    float* sA    = dsm + 16384;            // 32*SAS  = 4224
    float* s_smw = dsm + 16384 + 4224;     // 128*10  = 1280
    float* s_wf  = s_smw + 1280;           // 32*5    = 160

    const int tid = threadIdx.x;
    const int m0  = blockIdx.x * 32;
    const int tm  = tid >> 4;   // 0..15 -> rows tm*2..+1
    const int tn  = tid & 15;   // 0..15 -> cols tn*8..+7

    for (int i = tid; i < DH * 10; i += 256) s_smw[i] = smw[i];
    for (int i = tid; i < 160;     i += 256) s_wf[i]  = g_wf[(size_t)m0 * 5 + i];

    float moe[2][8];
    #pragma unroll
    for (int i = 0; i < 2; i++)
        #pragma unroll
        for (int j = 0; j < 8; j++) moe[i][j] = 0.f;

    for (int e = 0; e < NE; e++) {
        __syncthreads();
        for (int i = tid; i < (DH * DH) / 4; i += 256)
            ((float4*)sW)[i] = ((const float4*)(w2e + (size_t)e * DH * DH))[i];
        for (int i = tid; i < (32 * DH) / 4; i += 256) {
            int r = i / (DH / 4), c4 = i % (DH / 4);
            float4 v = *(const float4*)&g_h1[(size_t)(m0 + r) * (NE * DH) + e * DH + c4 * 4];
            *(float4*)&sA[r * SAS + c4 * 4] = v;
        }
        __syncthreads();

        float acc[2][8];
        #pragma unroll
        for (int i = 0; i < 2; i++)
            #pragma unroll
            for (int j = 0; j < 8; j++) acc[i][j] = 0.f;

        #pragma unroll 4
        for (int k = 0; k < DH; k++) {
            float a0 = sA[(tm * 2) * SAS + k];
            float a1 = sA[(tm * 2 + 1) * SAS + k];
            float4 bv0 = *(const float4*)&sW[k * DH + tn * 8];
            float4 bv1 = *(const float4*)&sW[k * DH + tn * 8 + 4];
            float bv[8] = {bv0.x, bv0.y, bv0.z, bv0.w, bv1.x, bv1.y, bv1.z, bv1.w};
            #pragma unroll
            for (int j = 0; j < 8; j++) {
                acc[0][j] += a0 * bv[j];
                acc[1][j] += a1 * bv[j];
            }
        }
        #pragma unroll
        for (int i = 0; i < 2; i++) {
            float wfe = s_wf[(tm * 2 + i) * 5 + e];
            #pragma unroll
            for (int j = 0; j < 8; j++)
                moe[i][j] += wfe * tanhf(acc[i][j] + b2e[e * DH + tn * 8 + j]);
        }
    }
    __syncthreads();
    #pragma unroll
    for (int i = 0; i < 2; i++)
        #pragma unroll
        for (int j = 0; j < 8; j++)
            sA[(tm * 2 + i) * SAS + tn * 8 + j] = moe[i][j];
    __syncthreads();

    if (tid < 32) {
        int r = tid;
        float lg[10];
        #pragma unroll
        for (int c = 0; c < 10; c++) lg[c] = smb[c];
        for (int k = 0; k < DH; k++) {
            float m = sA[r * SAS + k];
            #pragma unroll
            for (int c = 0; c < 10; c++) lg[c] += m * s_smw[k * 10 + c];
        }
        float mx = lg[0];
        #pragma unroll
        for (int c = 1; c < 10; c++) mx = fmaxf(mx, lg[c]);
        float ex[10], s = 0.f;
        #pragma unroll
        for (int c = 0; c < 10; c++) { ex[c] = expf(lg[c] - mx); s += ex[c]; }
        float inv = 1.0f / s;
        #pragma unroll
        for (int c = 0; c < 10; c++)
            out[(size_t)(m0 + r) * 10 + c] = ex[c] * inv;
    }
}

// ============================================================================
// launch
// ============================================================================
extern "C" void kernel_launch(void* const* d_in, const int* in_sizes, int n_in,
                              void* d_out, int out_size)
{
    (void)in_sizes; (void)n_in; (void)out_size;
    const float* x   = (const float*)d_in[0];
    const float* c1w = (const float*)d_in[1];
    const float* c1b = (const float*)d_in[2];
    const float* c2w = (const float*)d_in[3];
    const float* c2b = (const float*)d_in[4];
    const float* gw  = (const float*)d_in[5];
    const float* gb  = (const float*)d_in[6];
    const float* e1w = (const float*)d_in[7];
    const float* e1b = (const float*)d_in[8];
    const float* e2w = (const float*)d_in[9];
    const float* e2b = (const float*)d_in[10];
    const float* smw = (const float*)d_in[11];
    const float* smb = (const float*)d_in[12];
    float* out = (float*)d_out;

    const int dsmem = (16384 + 32 * SAS + 1280 + 160) * 4;
    cudaFuncSetAttribute(e2_head_kernel,
                         cudaFuncAttributeMaxDynamicSharedMemorySize, dsmem);

    conv_kernel<<<BATCH, 320>>>(x, c1w, c1b, c2w, c2b, gw, gb);
    e1_kernel<<<dim3(NE, BATCH / BM), 256>>>(e1w, e1b);
    e2_head_kernel<<<BATCH / 32, 256, dsmem>>>(e2w, e2b, smw, smb, out);
}